// round 9
// baseline (speedup 1.0000x reference)
#include <cuda_runtime.h>
#include <cuda_bf16.h>
#include <cstdint>

#define E_ 8
#define D_ 512
#define P_ 32
#define MTOK 64             // tokens per CTA; M = 128 rows (64 token + 64 anchor)
#define THREADS 256
#define FULLM 0xffffffffu

// padded bf16 row for B tile: 512 + 8 = 520 elems = 1040 B (ldmatrix conflict-free)
#define ROWB 1040

// ---- smem layout (bytes) ----
#define SM_B     0                       // 32 * 1040 = 33280; reused as cross[128][36] after MMA
#define SM_S2    33280                   // 128 floats
#define SM_P2    33792                   // 32 floats
#define SMEM_BYTES 33920
#define SM_CROSS 0
#define CSTRIDE  36                      // float4-aligned epilogue rows

__device__ int g_zero = 0;

static __device__ __forceinline__ uint32_t smem_u32(const void* p) {
    return (uint32_t)__cvta_generic_to_shared(p);
}

#define LDSM_X4(r0, r1, r2, r3, addr) \
    asm volatile("ldmatrix.sync.aligned.m8n8.x4.shared.b16 {%0,%1,%2,%3}, [%4];" \
        : "=r"(r0), "=r"(r1), "=r"(r2), "=r"(r3) : "r"(addr))

// 256-bit global load (sm_100+ PTX)
#define LDG256(f, ptr) \
    asm volatile("ld.global.nc.v8.f32 {%0,%1,%2,%3,%4,%5,%6,%7}, [%8];" \
        : "=f"((f)[0]), "=f"((f)[1]), "=f"((f)[2]), "=f"((f)[3]), \
          "=f"((f)[4]), "=f"((f)[5]), "=f"((f)[6]), "=f"((f)[7]) \
        : "l"(ptr))

static __device__ __forceinline__ void mma16816(float* d, const uint32_t* a,
                                                uint32_t b0, uint32_t b1) {
    asm volatile(
        "mma.sync.aligned.m16n8k16.row.col.f32.bf16.bf16.f32 "
        "{%0,%1,%2,%3}, {%4,%5,%6,%7}, {%8,%9}, {%0,%1,%2,%3};"
        : "+f"(d[0]), "+f"(d[1]), "+f"(d[2]), "+f"(d[3])
        : "r"(a[0]), "r"(a[1]), "r"(a[2]), "r"(a[3]), "r"(b0), "r"(b1));
}

static __device__ __forceinline__ uint32_t packbf(float x, float y) {
    __nv_bfloat162 h = __floats2bfloat162_rn(x, y);
    return *reinterpret_cast<uint32_t*>(&h);
}

__global__ __launch_bounds__(THREADS, 4)
void otng_hmma(const float* __restrict__ tokens,
               const float* __restrict__ protos,
               const int* __restrict__ fi_ptr,
               float* __restrict__ out, int B) {
    extern __shared__ char smem[];
    const int e    = blockIdx.x;
    const int fi   = *fi_ptr;
    const int b0   = blockIdx.y * MTOK;
    const int tid  = threadIdx.x;
    const int wid  = tid >> 5;
    const int lane = tid & 31;
    const int BE   = B * E_;

    if (e == fi) {                        // trivial expert
        if (tid < MTOK) {
            int b = b0 + tid;
            out[b * E_ + e]      = 1.0f;
            out[BE + b * E_ + e] = 0.0f;
        }
        return;
    }

    const uint32_t sbase = smem_u32(smem);
    float* s2s = (float*)(smem + SM_S2);
    float* p2s = (float*)(smem + SM_P2);

    // ---- stage B: 32 prototypes, superblock k-permutation (32 actual k per 64B) ----
    // superblock b holds actual k in [32b, 32b+32); lane-m of a quad owns kk=8m..8m+7.
    // frag0 (step 2b, bytes b*64+[0,32)):  pair(8m,8m+1)@m*4,   pair(8m+2,8m+3)@16+m*4
    // frag1 (step 2b+1, bytes b*64+[32,64)): pair(8m+4,8m+5)@m*4, pair(8m+6,8m+7)@16+m*4
    #pragma unroll 1
    for (int k = 0; k < 4; ++k) {
        const int p = wid + k * 8;                    // 0..31
        const float* src = protos + ((size_t)e * P_ + p) * D_;
        float nrm = 0.f;
        #pragma unroll
        for (int j = 0; j < 2; ++j) {
            const int c8 = j * 32 + lane;             // v8-chunk index, actual k = 8*c8
            float f[8];
            LDG256(f, src + 8 * c8);
            #pragma unroll
            for (int i = 0; i < 8; ++i) nrm = fmaf(f[i], f[i], nrm);
            const int bb = c8 >> 2;                   // superblock
            const int m  = c8 & 3;                    // quad slot
            char* base = smem + SM_B + p * ROWB + bb * 64 + m * 4;
            *reinterpret_cast<uint32_t*>(base)      = packbf(f[0], f[1]);
            *reinterpret_cast<uint32_t*>(base + 16) = packbf(f[2], f[3]);
            *reinterpret_cast<uint32_t*>(base + 32) = packbf(f[4], f[5]);
            *reinterpret_cast<uint32_t*>(base + 48) = packbf(f[6], f[7]);
        }
        #pragma unroll
        for (int o = 16; o; o >>= 1) nrm += __shfl_xor_sync(FULLM, nrm, o);
        if (lane == 0) p2s[p] = nrm;
    }
    __syncthreads();

    // ---- HMMA GEMM: A via 256-bit loads, one full 128B line per row per superblock ----
    float acc[16];
    #pragma unroll
    for (int i = 0; i < 16; ++i) acc[i] = 0.f;
    float nrm0 = 0.f, nrm1 = 0.f;
    {
        const int gr  = lane >> 2;
        const int m   = lane & 3;
        const int r0  = wid * 16 + gr;                // r1 = r0 + 8, same region
        const int col = (r0 < 64) ? e : fi;
        const int bt0 = b0 + (r0 & 63);
        const float* pA0 = tokens + ((size_t)bt0 * E_ + col) * D_ + 8 * m;
        const float* pA1 = tokens + ((size_t)(bt0 + 8) * E_ + col) * D_ + 8 * m;

        const int bn  = (lane & 7) + ((lane >> 4) << 3);
        const int bk  = ((lane >> 3) & 1) * 8;
        const uint32_t bAddr0 = sbase + SM_B + (uint32_t)bn * ROWB + (uint32_t)(bk * 2);
        const uint32_t bAddr1 = bAddr0 + 16u * ROWB;

        #pragma unroll 2
        for (int sb = 0; sb < 16; ++sb) {             // superblocks = 2 MMA steps each
            float x[8], y[8];
            LDG256(x, pA0 + sb * 32);                 // row r0,   kk = 8m..8m+7
            LDG256(y, pA1 + sb * 32);                 // row r0+8
            #pragma unroll
            for (int i = 0; i < 8; ++i) {
                nrm0 = fmaf(x[i], x[i], nrm0);
                nrm1 = fmaf(y[i], y[i], nrm1);
            }
            uint32_t a0[4], a1[4];
            a0[0] = packbf(x[0], x[1]); a0[1] = packbf(y[0], y[1]);
            a0[2] = packbf(x[2], x[3]); a0[3] = packbf(y[2], y[3]);
            a1[0] = packbf(x[4], x[5]); a1[1] = packbf(y[4], y[5]);
            a1[2] = packbf(x[6], x[7]); a1[3] = packbf(y[6], y[7]);

            uint32_t p0, p1, p2, p3, q0, q1, q2, q3;
            LDSM_X4(p0, p1, p2, p3, bAddr0 + sb * 64);        // step 2sb, n 0-15
            LDSM_X4(q0, q1, q2, q3, bAddr1 + sb * 64);        // step 2sb, n 16-31
            mma16816(acc + 0,  a0, p0, p1);
            mma16816(acc + 4,  a0, p2, p3);
            mma16816(acc + 8,  a0, q0, q1);
            mma16816(acc + 12, a0, q2, q3);

            LDSM_X4(p0, p1, p2, p3, bAddr0 + sb * 64 + 32);   // step 2sb+1
            LDSM_X4(q0, q1, q2, q3, bAddr1 + sb * 64 + 32);
            mma16816(acc + 0,  a1, p0, p1);
            mma16816(acc + 4,  a1, p2, p3);
            mma16816(acc + 8,  a1, q0, q1);
            mma16816(acc + 12, a1, q2, q3);
        }

        // row norms (fp32 pre-rounding): reduce across the quad (k pieces)
        nrm0 += __shfl_xor_sync(FULLM, nrm0, 1);
        nrm0 += __shfl_xor_sync(FULLM, nrm0, 2);
        nrm1 += __shfl_xor_sync(FULLM, nrm1, 1);
        nrm1 += __shfl_xor_sync(FULLM, nrm1, 2);
        if (m == 0) { s2s[r0] = nrm0; s2s[r0 + 8] = nrm1; }
    }
    __syncthreads();   // all ldsm reads of B done -> safe to overwrite with cross

    // ---- scatter accumulators to cross[128][36] (reuses B region) ----
    float* crossS = (float*)(smem + SM_CROSS);
    {
        const int r0 = wid * 16 + (lane >> 2);
        const int c0 = 2 * (lane & 3);
        #pragma unroll
        for (int nt = 0; nt < 4; ++nt) {
            const int col = nt * 8 + c0;
            *(float2*)(crossS + (size_t)r0 * CSTRIDE + col)       = make_float2(acc[nt*4+0], acc[nt*4+1]);
            *(float2*)(crossS + (size_t)(r0 + 8) * CSTRIDE + col) = make_float2(acc[nt*4+2], acc[nt*4+3]);
        }
    }
    __syncthreads();

    // ---- epilogue: quad = one token, lane holds 8 prototypes in registers ----
    // Sinkhorn fixed point: S(r) = sum_p 1/(1 + cp_p r) = 16; Newton from r=0 is
    // monotone-increasing & convergent (S convex decreasing, S(0)=32).
    {
        const int T  = tid >> 2;                      // token 0..63
        const int pl = (tid & 3) * 8;                 // this lane's 8 prototypes
        const float s2t = s2s[T];
        const float s2a = s2s[64 + T];

        float4 ct0 = *(const float4*)(crossS + (size_t)T * CSTRIDE + pl);
        float4 ct1 = *(const float4*)(crossS + (size_t)T * CSTRIDE + pl + 4);
        float4 ca0 = *(const float4*)(crossS + (size_t)(64 + T) * CSTRIDE + pl);
        float4 ca1 = *(const float4*)(crossS + (size_t)(64 + T) * CSTRIDE + pl + 4);
        float4 pv0 = *(const float4*)(p2s + pl);
        float4 pv1 = *(const float4*)(p2s + pl + 4);

        float ctv[8] = {ct0.x, ct0.y, ct0.z, ct0.w, ct1.x, ct1.y, ct1.z, ct1.w};
        float cav[8] = {ca0.x, ca0.y, ca0.z, ca0.w, ca1.x, ca1.y, ca1.z, ca1.w};
        float pvv[8] = {pv0.x, pv0.y, pv0.z, pv0.w, pv1.x, pv1.y, pv1.z, pv1.w};

        float cp[8], d01[8], sc1 = 0.f;
        #pragma unroll
        for (int j = 0; j < 8; ++j) {
            float c0 = fmaxf(fmaf(-2.f, ctv[j], s2t) + pvv[j], 0.f);
            float c1 = fmaxf(fmaf(-2.f, cav[j], s2a) + pvv[j], 0.f);
            d01[j] = c0 - c1;
            sc1   += c1;
            cp[j]  = __expf(20.f * (c0 - c1));        // kb/ka
        }

        float r = 0.f;
        #pragma unroll 1
        for (int it = 0; it < 8; ++it) {
            float f = 0.f, g = 0.f;
            #pragma unroll
            for (int j = 0; j < 8; ++j) {
                float u = __frcp_rn(fmaf(cp[j], r, 1.f));
                f += u;
                g = fmaf(cp[j], u * u, g);
            }
            f += __shfl_xor_sync(FULLM, f, 1);
            f += __shfl_xor_sync(FULLM, f, 2);
            g += __shfl_xor_sync(FULLM, g, 1);
            g += __shfl_xor_sync(FULLM, g, 2);
            r = fmaf(f - 16.f, __frcp_rn(g), r);
        }

        float ot = sc1;
        #pragma unroll
        for (int j = 0; j < 8; ++j) {
            float w = __frcp_rn(fmaf(cp[j], r, 1.f));
            ot = fmaf(w, d01[j], ot);                 // sum_p [w*d01 + c1]
        }
        ot += __shfl_xor_sync(FULLM, ot, 1);
        ot += __shfl_xor_sync(FULLM, ot, 2);

        if ((tid & 3) == 0) {
            const int b = b0 + T;
            float o_  = ot * (1.f / 32.f);
            float val = __fdividef(1.f, 1.f + __expf(6.f * (o_ - 0.25f)));
            out[b * E_ + e]      = val;
            out[BE + b * E_ + e] = o_;
        }
    }
}

// ---------------- launch ----------------
extern "C" void kernel_launch(void* const* d_in, const int* in_sizes, int n_in,
                              void* d_out, int out_size) {
    const float* tokens = (const float*)d_in[0];
    const float* protos = (const float*)d_in[1];
    const int* fi;
    if (n_in >= 3) {
        fi = (const int*)d_in[2];
    } else {
        void* zp = nullptr;
        cudaGetSymbolAddress(&zp, g_zero);
        fi = (const int*)zp;
    }
    float* out = (float*)d_out;
    const int B = in_sizes[0] / (E_ * D_);

    cudaFuncSetAttribute(otng_hmma,
                         cudaFuncAttributeMaxDynamicSharedMemorySize, SMEM_BYTES);
    dim3 grid(E_, B / MTOK);
    otng_hmma<<<grid, THREADS, SMEM_BYTES>>>(tokens, protos, fi, out, B);
}

// round 10
// speedup vs baseline: 1.0446x; 1.0446x over previous
#include <cuda_runtime.h>
#include <cuda_bf16.h>
#include <cstdint>

#define E_ 8
#define D_ 512
#define P_ 32
#define MTOK 64             // tokens per CTA; M = 128 rows (64 token + 64 anchor)
#define THREADS 256
#define FULLM 0xffffffffu

// padded bf16 row for B tile: 512 + 8 = 520 elems = 1040 B (ldmatrix conflict-free)
#define ROWB 1040

// ---- smem layout (bytes) ----
#define SM_B     0                       // 32 * 1040 = 33280; reused as cross[128][36] after MMA
#define SM_S2    33280                   // 128 floats
#define SM_P2    33792                   // 32 floats
#define SMEM_BYTES 33920
#define SM_CROSS 0
#define CSTRIDE  36                      // float4-aligned epilogue rows

__device__ int g_zero = 0;

static __device__ __forceinline__ uint32_t smem_u32(const void* p) {
    return (uint32_t)__cvta_generic_to_shared(p);
}

#define LDSM_X4(r0, r1, r2, r3, addr) \
    asm volatile("ldmatrix.sync.aligned.m8n8.x4.shared.b16 {%0,%1,%2,%3}, [%4];" \
        : "=r"(r0), "=r"(r1), "=r"(r2), "=r"(r3) : "r"(addr))

static __device__ __forceinline__ void mma16816(float* d, const uint32_t* a,
                                                uint32_t b0, uint32_t b1) {
    asm volatile(
        "mma.sync.aligned.m16n8k16.row.col.f32.bf16.bf16.f32 "
        "{%0,%1,%2,%3}, {%4,%5,%6,%7}, {%8,%9}, {%0,%1,%2,%3};"
        : "+f"(d[0]), "+f"(d[1]), "+f"(d[2]), "+f"(d[3])
        : "r"(a[0]), "r"(a[1]), "r"(a[2]), "r"(a[3]), "r"(b0), "r"(b1));
}

static __device__ __forceinline__ uint32_t packbf(float x, float y) {
    __nv_bfloat162 h = __floats2bfloat162_rn(x, y);
    return *reinterpret_cast<uint32_t*>(&h);
}

__global__ __launch_bounds__(THREADS, 4)
void otng_hmma(const float* __restrict__ tokens,
               const float* __restrict__ protos,
               const int* __restrict__ fi_ptr,
               float* __restrict__ out, int B) {
    extern __shared__ char smem[];
    const int e    = blockIdx.x;
    const int fi   = *fi_ptr;
    const int b0   = blockIdx.y * MTOK;
    const int tid  = threadIdx.x;
    const int wid  = tid >> 5;
    const int lane = tid & 31;
    const int BE   = B * E_;

    if (e == fi) {                        // trivial expert
        if (tid < MTOK) {
            int b = b0 + tid;
            out[b * E_ + e]      = 1.0f;
            out[BE + b * E_ + e] = 0.0f;
        }
        return;
    }

    const uint32_t sbase = smem_u32(smem);
    float* s2s = (float*)(smem + SM_S2);
    float* p2s = (float*)(smem + SM_P2);

    // ---- stage B: 32 prototypes of expert e, K-PERMUTED within each 16-k block ----
    // actual k = 4q..4q+3 goes to frag slots {2q, 2q+1} and {8+2q, 8+2q+1}.
    #pragma unroll 1
    for (int k = 0; k < 4; ++k) {
        const int p = wid + k * 8;                    // 0..31
        const float4* src = (const float4*)(protos + ((size_t)e * P_ + p) * D_);
        float nrm = 0.f;
        #pragma unroll
        for (int j = 0; j < 4; ++j) {
            float4 v = src[j * 32 + lane];            // actual k = j*128 + lane*4
            nrm = fmaf(v.x, v.x, fmaf(v.y, v.y, fmaf(v.z, v.z, fmaf(v.w, v.w, nrm))));
            const uint32_t blk = (uint32_t)(j * 8 + (lane >> 2));   // 16-k block idx
            const uint32_t q   = (uint32_t)(lane & 3);
            const uint32_t base = (uint32_t)(p * ROWB) + blk * 32u + q * 4u;
            *reinterpret_cast<uint32_t*>(smem + SM_B + base)      = packbf(v.x, v.y);
            *reinterpret_cast<uint32_t*>(smem + SM_B + base + 16) = packbf(v.z, v.w);
        }
        #pragma unroll
        for (int o = 16; o; o >>= 1) nrm += __shfl_xor_sync(FULLM, nrm, o);
        if (lane == 0) p2s[p] = nrm;
    }
    __syncthreads();

    // ---- HMMA GEMM, A via LDG.128 with depth-1 software prefetch (k-permuted) ----
    float acc[16];
    #pragma unroll
    for (int i = 0; i < 16; ++i) acc[i] = 0.f;
    float nrm0 = 0.f, nrm1 = 0.f;
    {
        const int gr  = lane >> 2;
        const int m   = lane & 3;
        const int r0  = wid * 16 + gr;                // r1 = r0 + 8, same region
        const int col = (r0 < 64) ? e : fi;
        const int bt0 = b0 + (r0 & 63);
        const float4* gA0 = (const float4*)(tokens + ((size_t)bt0 * E_ + col) * D_ + 4 * m);
        const float4* gA1 = (const float4*)(tokens + ((size_t)(bt0 + 8) * E_ + col) * D_ + 4 * m);

        const int bn  = (lane & 7) + ((lane >> 4) << 3);
        const int bk  = ((lane >> 3) & 1) * 8;
        const uint32_t bAddr0 = sbase + SM_B + (uint32_t)bn * ROWB + (uint32_t)(bk * 2);
        const uint32_t bAddr1 = bAddr0 + 16u * ROWB;

        float4 v0 = gA0[0];
        float4 v1 = gA1[0];

        #pragma unroll 4
        for (int s = 0; s < 32; ++s) {
            const int sn = (s + 1) & 31;              // branchless wrap (harmless L1 hit)
            float4 n0 = gA0[sn * 4];
            float4 n1 = gA1[sn * 4];

            uint32_t a[4];
            a[0] = packbf(v0.x, v0.y); a[2] = packbf(v0.z, v0.w);
            a[1] = packbf(v1.x, v1.y); a[3] = packbf(v1.z, v1.w);
            nrm0 = fmaf(v0.x, v0.x, fmaf(v0.y, v0.y, fmaf(v0.z, v0.z, fmaf(v0.w, v0.w, nrm0))));
            nrm1 = fmaf(v1.x, v1.x, fmaf(v1.y, v1.y, fmaf(v1.z, v1.z, fmaf(v1.w, v1.w, nrm1))));

            uint32_t p0, p1, p2, p3, q0, q1, q2, q3;
            LDSM_X4(p0, p1, p2, p3, bAddr0 + s * 32);
            LDSM_X4(q0, q1, q2, q3, bAddr1 + s * 32);
            mma16816(acc + 0,  a, p0, p1);   // n 0-7
            mma16816(acc + 4,  a, p2, p3);   // n 8-15
            mma16816(acc + 8,  a, q0, q1);   // n 16-23
            mma16816(acc + 12, a, q2, q3);   // n 24-31

            v0 = n0; v1 = n1;
        }

        // row norms (fp32 pre-rounding): reduce across the quad (k pieces)
        nrm0 += __shfl_xor_sync(FULLM, nrm0, 1);
        nrm0 += __shfl_xor_sync(FULLM, nrm0, 2);
        nrm1 += __shfl_xor_sync(FULLM, nrm1, 1);
        nrm1 += __shfl_xor_sync(FULLM, nrm1, 2);
        if (m == 0) { s2s[r0] = nrm0; s2s[r0 + 8] = nrm1; }
    }
    __syncthreads();   // all ldsm reads of B done -> safe to overwrite with cross

    // ---- scatter accumulators to cross[128][36] (reuses B region) ----
    float* crossS = (float*)(smem + SM_CROSS);
    {
        const int r0 = wid * 16 + (lane >> 2);
        const int c0 = 2 * (lane & 3);
        #pragma unroll
        for (int nt = 0; nt < 4; ++nt) {
            const int col = nt * 8 + c0;
            *(float2*)(crossS + (size_t)r0 * CSTRIDE + col)       = make_float2(acc[nt*4+0], acc[nt*4+1]);
            *(float2*)(crossS + (size_t)(r0 + 8) * CSTRIDE + col) = make_float2(acc[nt*4+2], acc[nt*4+3]);
        }
    }
    __syncthreads();

    // ---- epilogue: quad = one token, lane holds 8 prototypes in registers ----
    // Sinkhorn fixed point: S(r) = sum_p 1/(1 + cp_p r) = 16; Newton from r=0 is
    // monotone-increasing & convergent (S convex decreasing, S(0)=32).
    {
        const int T  = tid >> 2;                      // token 0..63
        const int pl = (tid & 3) * 8;                 // this lane's 8 prototypes
        const float s2t = s2s[T];
        const float s2a = s2s[64 + T];

        float4 ct0 = *(const float4*)(crossS + (size_t)T * CSTRIDE + pl);
        float4 ct1 = *(const float4*)(crossS + (size_t)T * CSTRIDE + pl + 4);
        float4 ca0 = *(const float4*)(crossS + (size_t)(64 + T) * CSTRIDE + pl);
        float4 ca1 = *(const float4*)(crossS + (size_t)(64 + T) * CSTRIDE + pl + 4);
        float4 pv0 = *(const float4*)(p2s + pl);
        float4 pv1 = *(const float4*)(p2s + pl + 4);

        float ctv[8] = {ct0.x, ct0.y, ct0.z, ct0.w, ct1.x, ct1.y, ct1.z, ct1.w};
        float cav[8] = {ca0.x, ca0.y, ca0.z, ca0.w, ca1.x, ca1.y, ca1.z, ca1.w};
        float pvv[8] = {pv0.x, pv0.y, pv0.z, pv0.w, pv1.x, pv1.y, pv1.z, pv1.w};

        float cp[8], d01[8], sc1 = 0.f;
        #pragma unroll
        for (int j = 0; j < 8; ++j) {
            float c0 = fmaxf(fmaf(-2.f, ctv[j], s2t) + pvv[j], 0.f);
            float c1 = fmaxf(fmaf(-2.f, cav[j], s2a) + pvv[j], 0.f);
            d01[j] = c0 - c1;
            sc1   += c1;
            cp[j]  = __expf(20.f * (c0 - c1));        // kb/ka
        }

        float r = 0.f;
        #pragma unroll 1
        for (int it = 0; it < 6; ++it) {
            float f = 0.f, g = 0.f;
            #pragma unroll
            for (int j = 0; j < 8; ++j) {
                float u = __frcp_rn(fmaf(cp[j], r, 1.f));
                f += u;
                g = fmaf(cp[j], u * u, g);
            }
            f += __shfl_xor_sync(FULLM, f, 1);
            f += __shfl_xor_sync(FULLM, f, 2);
            g += __shfl_xor_sync(FULLM, g, 1);
            g += __shfl_xor_sync(FULLM, g, 2);
            r = fmaf(f - 16.f, __frcp_rn(g), r);
        }

        float ot = sc1;
        #pragma unroll
        for (int j = 0; j < 8; ++j) {
            float w = __frcp_rn(fmaf(cp[j], r, 1.f));
            ot = fmaf(w, d01[j], ot);                 // sum_p [w*d01 + c1]
        }
        ot += __shfl_xor_sync(FULLM, ot, 1);
        ot += __shfl_xor_sync(FULLM, ot, 2);

        if ((tid & 3) == 0) {
            const int b = b0 + T;
            float o_  = ot * (1.f / 32.f);
            float val = __fdividef(1.f, 1.f + __expf(6.f * (o_ - 0.25f)));
            out[b * E_ + e]      = val;
            out[BE + b * E_ + e] = o_;
        }
    }
}

// ---------------- launch ----------------
extern "C" void kernel_launch(void* const* d_in, const int* in_sizes, int n_in,
                              void* d_out, int out_size) {
    const float* tokens = (const float*)d_in[0];
    const float* protos = (const float*)d_in[1];
    const int* fi;
    if (n_in >= 3) {
        fi = (const int*)d_in[2];
    } else {
        void* zp = nullptr;
        cudaGetSymbolAddress(&zp, g_zero);
        fi = (const int*)zp;
    }
    float* out = (float*)d_out;
    const int B = in_sizes[0] / (E_ * D_);

    cudaFuncSetAttribute(otng_hmma,
                         cudaFuncAttributeMaxDynamicSharedMemorySize, SMEM_BYTES);
    dim3 grid(E_, B / MTOK);
    otng_hmma<<<grid, THREADS, SMEM_BYTES>>>(tokens, protos, fi, out, B);
}